// round 9
// baseline (speedup 1.0000x reference)
#include <cuda_runtime.h>
#include <cuda_bf16.h>
#include <cstdint>

#define Bb 8
#define Ss 1024
#define Dd 768
#define Hh 12
#define HDd 64
#define BH (Bb*Hh)
#define LDA 80    // 32 bf16 + 8B pad (proj/pv-style tiles)
#define LDA64 144 // 64 bf16 + 16B pad (attn K/Q tiles)
#define LDP 528   // 256 bf16 + 16B pad (attn P quarter tiles)

// ---------------- device scratch (statics; no runtime allocs) ------------
__device__ __nv_bfloat16 g_Qhi[(size_t)BH * Ss * HDd];
__device__ __nv_bfloat16 g_Qlo[(size_t)BH * Ss * HDd];
__device__ __nv_bfloat16 g_Khi[(size_t)BH * Ss * HDd];
__device__ __nv_bfloat16 g_Klo[(size_t)BH * Ss * HDd];
__device__ __nv_bfloat16 g_Vthi[(size_t)BH * HDd * Ss];   // [B,H,HD,S]
__device__ __nv_bfloat16 g_Vtlo[(size_t)BH * HDd * Ss];
__device__ float g_rel[(size_t)Bb * Ss * Ss];             // rel_attn (head-indep)
__device__ unsigned char g_mask[(size_t)Bb * Ss * Ss];
__device__ int g_mmode;

// ======================= MMA primitives (plain sm_80+ PTX) ===============
__device__ __forceinline__ unsigned smem_u32(const void* p) {
    unsigned a;
    asm("{ .reg .u64 t; cvta.to.shared.u64 t, %1; cvt.u32.u64 %0, t; }" : "=r"(a) : "l"(p));
    return a;
}
__device__ __forceinline__ void ldmA(unsigned* a, unsigned addr) {
    asm volatile("ldmatrix.sync.aligned.m8n8.x4.shared.b16 {%0,%1,%2,%3}, [%4];"
        : "=r"(a[0]), "=r"(a[1]), "=r"(a[2]), "=r"(a[3]) : "r"(addr));
}
__device__ __forceinline__ void ldmB(unsigned* b, unsigned addr) {
    asm volatile("ldmatrix.sync.aligned.m8n8.x2.shared.b16 {%0,%1}, [%2];"
        : "=r"(b[0]), "=r"(b[1]) : "r"(addr));
}
__device__ __forceinline__ void mma16816(float* d, const unsigned* a, const unsigned* b) {
    asm volatile("mma.sync.aligned.m16n8k16.row.col.f32.bf16.bf16.f32 "
        "{%0,%1,%2,%3}, {%4,%5,%6,%7}, {%8,%9}, {%0,%1,%2,%3};"
        : "+f"(d[0]), "+f"(d[1]), "+f"(d[2]), "+f"(d[3])
        : "r"(a[0]), "r"(a[1]), "r"(a[2]), "r"(a[3]), "r"(b[0]), "r"(b[1]));
}

// fp32 -> bf16 hi/lo split; store 4 elems (8B) per side at byte offset 'off'
__device__ __forceinline__ void cvt8(char* hi, char* lo, unsigned off, float4 f) {
    __nv_bfloat162 h0 = __float22bfloat162_rn(make_float2(f.x, f.y));
    __nv_bfloat162 h1 = __float22bfloat162_rn(make_float2(f.z, f.w));
    float2 g0 = __bfloat1622float2(h0);
    float2 g1 = __bfloat1622float2(h1);
    __nv_bfloat162 m0 = __float22bfloat162_rn(make_float2(f.x - g0.x, f.y - g0.y));
    __nv_bfloat162 m1 = __float22bfloat162_rn(make_float2(f.z - g1.x, f.w - g1.y));
    uint2 uh; uh.x = *(unsigned*)&h0; uh.y = *(unsigned*)&h1;
    uint2 ul; ul.x = *(unsigned*)&m0; ul.y = *(unsigned*)&m1;
    *(uint2*)(hi + off) = uh;
    *(uint2*)(lo + off) = ul;
}

template<int NF4> struct R4 { float4 v[NF4]; };
template<int NF4>
__device__ __forceinline__ void gload(const float* __restrict__ src, int stride, R4<NF4>& rg, int tid) {
#pragma unroll
    for (int t = 0; t < NF4; t++) {
        int i = tid + t * 256;
        rg.v[t] = *(const float4*)(src + (long)(i >> 3) * stride + (i & 7) * 4);
    }
}
template<int NF4>
__device__ __forceinline__ void cstore(char* hi, char* lo, const R4<NF4>& rg, int tid) {
#pragma unroll
    for (int t = 0; t < NF4; t++) {
        int i = tid + t * 256;
        cvt8(hi, lo, (unsigned)((i >> 3) * LDA + (i & 7) * 8), rg.v[t]);
    }
}

// one K=32 chunk of 3-pass split MMA (proj: 128x128 tile, LDA=80)
__device__ __forceinline__ void mma_chunk(float (&c)[4][4][4], unsigned sb,
                                          int lane, int warp_m, int warp_n) {
    unsigned aOff = sb + (unsigned)(warp_m * 64 + (lane & 15)) * LDA + ((lane >> 4) & 1) * 16;
    unsigned bOff = sb + 20480u + (unsigned)(warp_n * 32 + (lane & 7)) * LDA + ((lane >> 3) & 1) * 16;
#pragma unroll
    for (int ks = 0; ks < 2; ks++) {
        unsigned ah[4][4], al[4][4];
#pragma unroll
        for (int ma = 0; ma < 4; ma++) {
            ldmA(ah[ma], aOff + ma * 16 * LDA + ks * 32);
            ldmA(al[ma], aOff + 10240u + ma * 16 * LDA + ks * 32);
        }
#pragma unroll
        for (int na = 0; na < 4; na++) {
            unsigned bh[2], bl[2];
            ldmB(bh, bOff + na * 8 * LDA + ks * 32);
            ldmB(bl, bOff + 128u * LDA + na * 8 * LDA + ks * 32);
#pragma unroll
            for (int ma = 0; ma < 4; ma++) {
                mma16816(c[ma][na], ah[ma], bh);
                mma16816(c[ma][na], ah[ma], bl);
                mma16816(c[ma][na], al[ma], bh);
            }
        }
    }
}

// fast exp on the FFMA pipe (~1.3e-5 rel err)
__device__ __forceinline__ float fexp(float x) {
    float t = fmaxf(x * 1.4426950408889634f, -126.0f);
    float fi = floorf(t);
    float f = t - fi;
    float p = 1.5403530394e-4f;
    p = fmaf(p, f, 1.3333558146e-3f);
    p = fmaf(p, f, 9.6181291076e-3f);
    p = fmaf(p, f, 5.5504108664e-2f);
    p = fmaf(p, f, 2.4022650696e-1f);
    p = fmaf(p, f, 6.9314718056e-1f);
    p = fmaf(p, f, 1.0f);
    return p * __int_as_float(((int)fi + 127) << 23);
}

__device__ __forceinline__ void split1(float v, __nv_bfloat16& h, __nv_bfloat16& l) {
    h = __float2bfloat16(v);
    l = __float2bfloat16(v - __bfloat162float(h));
}

// ---------------- mask detect + convert ----------------------------------
__global__ void mask_detect_kernel(const void* mp) {
    __shared__ int allf, alli;
    if (threadIdx.x == 0) { allf = 1; alli = 1; }
    __syncthreads();
    float v = ((const float*)mp)[threadIdx.x];
    int iv = ((const int*)mp)[threadIdx.x];
    if (!(v == 0.0f || v == 1.0f)) allf = 0;
    if (!(iv == 0 || iv == 1)) alli = 0;
    __syncthreads();
    if (threadIdx.x == 0) g_mmode = allf ? 0 : (alli ? 1 : 2);
}
__global__ void mask_convert_kernel(const void* mp) {
    size_t i = (size_t)blockIdx.x * blockDim.x + threadIdx.x;
    int mode = g_mmode;
    unsigned char m;
    if (mode == 0)      m = (((const float*)mp)[i] != 0.0f);
    else if (mode == 1) m = (((const int*)mp)[i] != 0);
    else                m = (((const unsigned char*)mp)[i] != 0);
    g_mask[i] = m;
}

// ---------------- rel_attn softmax (head-independent) --------------------
__global__ void __launch_bounds__(256)
rel_softmax_kernel(const float* __restrict__ rel) {
    __shared__ float red[8];
    int row = blockIdx.x;
    const float* r = rel + (size_t)row * Ss;
    const unsigned char* m = g_mask + (size_t)row * Ss;
    int tid = threadIdx.x, w = tid >> 5, l = tid & 31;

    float4 rf = *(const float4*)(r + tid * 4);
    uchar4 mk = *(const uchar4*)(m + tid * 4);
    float v[4];
    v[0] = mk.x ? rf.x : 0.0f; v[1] = mk.y ? rf.y : 0.0f;
    v[2] = mk.z ? rf.z : 0.0f; v[3] = mk.w ? rf.w : 0.0f;
    float mx = -3e38f;
#pragma unroll
    for (int j = 0; j < 4; j++) {
        v[j] = (v[j] == 0.0f) ? -10000.0f : v[j];
        mx = fmaxf(mx, v[j]);
    }
#pragma unroll
    for (int o = 16; o; o >>= 1) mx = fmaxf(mx, __shfl_xor_sync(0xffffffffu, mx, o));
    if (l == 0) red[w] = mx;
    __syncthreads();
    if (w == 0) {
        float t = (l < 8) ? red[l] : -3e38f;
#pragma unroll
        for (int o = 4; o; o >>= 1) t = fmaxf(t, __shfl_xor_sync(0xffffffffu, t, o));
        if (l == 0) red[0] = t;
    }
    __syncthreads();
    mx = red[0];
    __syncthreads();
    float e[4], sum = 0.0f;
#pragma unroll
    for (int j = 0; j < 4; j++) { e[j] = fexp(v[j] - mx); sum += e[j]; }
#pragma unroll
    for (int o = 16; o; o >>= 1) sum += __shfl_xor_sync(0xffffffffu, sum, o);
    if (l == 0) red[w] = sum;
    __syncthreads();
    if (w == 0) {
        float t = (l < 8) ? red[l] : 0.0f;
#pragma unroll
        for (int o = 4; o; o >>= 1) t += __shfl_xor_sync(0xffffffffu, t, o);
        if (l == 0) red[0] = t;
    }
    __syncthreads();
    float inv = 1.0f / red[0];
    float4 o;
    o.x = e[0] * inv; o.y = e[1] * inv; o.z = e[2] * inv; o.w = e[3] * inv;
    *(float4*)(g_rel + (size_t)row * Ss + tid * 4) = o;
}

// ================= projection GEMM (bf16x3 mma.sync) =====================
// Outputs pre-split bf16 hi/lo: Q,K -> [B,H,S,HD]; V -> transposed [B,H,HD,S]
#define PROJ_SMEM (2 * 40960)
__global__ void __launch_bounds__(256, 1)
proj_mma(const float* __restrict__ Xq, const float* __restrict__ Xk, const float* __restrict__ Xv,
         const float* __restrict__ Wq, const float* __restrict__ Wk, const float* __restrict__ Wv,
         const float* __restrict__ bqp, const float* __restrict__ bkp, const float* __restrict__ bvp) {
    extern __shared__ char sm[];
    unsigned smb = smem_u32(sm);
    int tid = threadIdx.x, lane = tid & 31, wid = tid >> 5;
    int warp_m = wid >> 2, warp_n = wid & 3;
    int z = blockIdx.z;
    const float* X = (z == 0) ? Xq : (z == 1) ? Xk : Xv;
    const float* W = (z == 0) ? Wq : (z == 1) ? Wk : Wv;
    const float* bias = (z == 0) ? bqp : (z == 1) ? bkp : bvp;
    int j0 = blockIdx.x * 128, i0 = blockIdx.y * 128;

    float acc[4][4][4];
#pragma unroll
    for (int a = 0; a < 4; a++)
#pragma unroll
        for (int b = 0; b < 4; b++)
#pragma unroll
            for (int r = 0; r < 4; r++) acc[a][b][r] = 0.0f;

    const float* A0 = X + (size_t)i0 * Dd;
    const float* B0 = W + (size_t)j0 * Dd;
    R4<4> ra, rb;
    gload<4>(A0, Dd, ra, tid);
    gload<4>(B0, Dd, rb, tid);
    cstore<4>(sm, sm + 10240, ra, tid);
    cstore<4>(sm + 20480, sm + 30720, rb, tid);
    __syncthreads();

    const int NC = Dd / 32;
    for (int cc = 0; cc < NC; cc++) {
        if (cc + 1 < NC) {
            gload<4>(A0 + (cc + 1) * 32, Dd, ra, tid);
            gload<4>(B0 + (cc + 1) * 32, Dd, rb, tid);
        }
        mma_chunk(acc, smb + (unsigned)(cc & 1) * 40960u, lane, warp_m, warp_n);
        if (cc + 1 < NC) {
            char* bn = sm + ((cc + 1) & 1) * 40960;
            cstore<4>(bn, bn + 10240, ra, tid);
            cstore<4>(bn + 20480, bn + 30720, rb, tid);
        }
        __syncthreads();
    }

    int bI = i0 >> 10, sbase = i0 & 1023;
    float bias2[4][2];
#pragma unroll
    for (int na = 0; na < 4; na++) {
        int n0 = warp_n * 32 + na * 8 + (lane & 3) * 2;
        bias2[na][0] = bias[j0 + n0];
        bias2[na][1] = bias[j0 + n0 + 1];
    }
    if (z == 2) {
#pragma unroll
        for (int ma = 0; ma < 4; ma++)
#pragma unroll
            for (int na = 0; na < 4; na++)
#pragma unroll
                for (int rp = 0; rp < 2; rp++) {
                    int m = warp_m * 64 + ma * 16 + (lane >> 2) + rp * 8;
                    int n0 = warp_n * 32 + na * 8 + (lane & 3) * 2;
                    int j = j0 + n0, h = j >> 6, hd = j & 63;
                    int s = sbase + m;
                    float v0 = acc[ma][na][rp * 2]     + bias2[na][0];
                    float v1 = acc[ma][na][rp * 2 + 1] + bias2[na][1];
                    __nv_bfloat16 h0, l0, h1, l1;
                    split1(v0, h0, l0); split1(v1, h1, l1);
                    size_t base = ((size_t)bI * Hh + h) * HDd;
                    g_Vthi[(base + hd)     * Ss + s] = h0;
                    g_Vtlo[(base + hd)     * Ss + s] = l0;
                    g_Vthi[(base + hd + 1) * Ss + s] = h1;
                    g_Vtlo[(base + hd + 1) * Ss + s] = l1;
                }
    } else {
        __nv_bfloat16* Ohi = (z == 0) ? g_Qhi : g_Khi;
        __nv_bfloat16* Olo = (z == 0) ? g_Qlo : g_Klo;
#pragma unroll
        for (int ma = 0; ma < 4; ma++)
#pragma unroll
            for (int na = 0; na < 4; na++)
#pragma unroll
                for (int rp = 0; rp < 2; rp++) {
                    int m = warp_m * 64 + ma * 16 + (lane >> 2) + rp * 8;
                    int n0 = warp_n * 32 + na * 8 + (lane & 3) * 2;
                    int j = j0 + n0, h = j >> 6, hd = j & 63;
                    float v0 = acc[ma][na][rp * 2]     + bias2[na][0];
                    float v1 = acc[ma][na][rp * 2 + 1] + bias2[na][1];
                    __nv_bfloat16 h0, l0, h1, l1;
                    split1(v0, h0, l0); split1(v1, h1, l1);
                    size_t idx = (((size_t)bI * Hh + h) * Ss + sbase + m) * HDd + hd;
                    __nv_bfloat162 ph; ph.x = h0; ph.y = h1;
                    __nv_bfloat162 pl; pl.x = l0; pl.y = l1;
                    *(__nv_bfloat162*)(Ohi + idx) = ph;
                    *(__nv_bfloat162*)(Olo + idx) = pl;
                }
    }
}

// ====== mega-fused attention: QK^T -> softmax -> mix -> prob + PV -> out ==
// block = (qtile 32, h, b); 256 threads (8 warps).
// SMEM: [scores 32x1028 f32 = 131584][Q hi/lo 9216][K dbl-buf 73728] = 214528
// phase3 reuses [K region]: [P quarter hi/lo 33792][V dbl-buf 20480]
#define FA_Q     131584
#define FA_K     140800
#define FA_KLO   18432
#define FA_KBUF  36864
#define FA_P     140800
#define FA_PLO   16896
#define FA_V     (FA_P + 33792)
#define FA_VBUF  10240
#define FA_VLO   5120
#define FA_SMEM  214528
__global__ void __launch_bounds__(256, 1)
fused_attn(const float* __restrict__ l1p, float* __restrict__ probp, float* __restrict__ outp) {
    extern __shared__ char sm[];
    unsigned smb = smem_u32(sm);
    float* sS = (float*)sm;
    int tid = threadIdx.x, lane = tid & 31, wid = tid >> 5;
    int warp_m = wid >> 2, warp_n = wid & 3;   // phase1: 2x4 (16q x 32k)
    int q0 = blockIdx.x * 32, h = blockIdx.y, b = blockIdx.z;
    size_t bh = (size_t)b * Hh + h;

    // ---- load Q tile (pre-split) : 512 uint4 ----
    {
        const __nv_bfloat16* qs[2] = { g_Qhi + (bh * Ss + q0) * HDd, g_Qlo + (bh * Ss + q0) * HDd };
#pragma unroll
        for (int t = 0; t < 2; t++) {
            int idx = tid + t * 256;
            int side = idx >> 8, r = (idx >> 3) & 31, c = idx & 7;
            uint4 u = *(const uint4*)(qs[side] + (size_t)r * HDd + c * 8);
            *(uint4*)(sm + FA_Q + side * 4608 + r * LDA64 + c * 16) = u;
        }
    }
    // ---- K tile 0 ----
    const __nv_bfloat16* Khi = g_Khi + bh * Ss * HDd;
    const __nv_bfloat16* Klo = g_Klo + bh * Ss * HDd;
    uint4 kreg[8];
#pragma unroll
    for (int t = 0; t < 8; t++) {
        int idx = tid + t * 256;
        int side = idx >> 10, r = (idx >> 3) & 127, c = idx & 7;
        const __nv_bfloat16* src = (side ? Klo : Khi) + (size_t)r * HDd + c * 8;
        kreg[t] = *(const uint4*)src;
    }
#pragma unroll
    for (int t = 0; t < 8; t++) {
        int idx = tid + t * 256;
        int side = idx >> 10, r = (idx >> 3) & 127, c = idx & 7;
        *(uint4*)(sm + FA_K + side * FA_KLO + r * LDA64 + c * 16) = kreg[t];
    }
    __syncthreads();

    unsigned aBase = smb + FA_Q + (unsigned)(warp_m * 16 + (lane & 15)) * LDA64 + ((lane >> 4) & 1) * 16;
    // ---------------- phase 1: raw scores into SMEM ----------------
    for (int kt = 0; kt < 8; kt++) {
        if (kt < 7) {
#pragma unroll
            for (int t = 0; t < 8; t++) {
                int idx = tid + t * 256;
                int side = idx >> 10, r = (idx >> 3) & 127, c = idx & 7;
                const __nv_bfloat16* src = (side ? Klo : Khi) + ((size_t)(kt + 1) * 128 + r) * HDd + c * 8;
                kreg[t] = *(const uint4*)src;
            }
        }
        unsigned bBase = smb + FA_K + (unsigned)(kt & 1) * FA_KBUF
                       + (unsigned)(warp_n * 32 + (lane & 7)) * LDA64 + ((lane >> 3) & 1) * 16;
        float acc[4][4];
#pragma unroll
        for (int na = 0; na < 4; na++)
#pragma unroll
            for (int r = 0; r < 4; r++) acc[na][r] = 0.0f;
#pragma unroll
        for (int ks = 0; ks < 4; ks++) {
            unsigned ah[4], al[4];
            ldmA(ah, aBase + ks * 32);
            ldmA(al, aBase + 4608 + ks * 32);
#pragma unroll
            for (int na = 0; na < 4; na++) {
                unsigned bhF[2], blF[2];
                ldmB(bhF, bBase + na * 8 * LDA64 + ks * 32);
                ldmB(blF, bBase + FA_KLO + na * 8 * LDA64 + ks * 32);
                mma16816(acc[na], ah, bhF);
                mma16816(acc[na], ah, blF);
                mma16816(acc[na], al, bhF);
            }
        }
#pragma unroll
        for (int na = 0; na < 4; na++)
#pragma unroll
            for (int rp = 0; rp < 2; rp++) {
                int m = warp_m * 16 + (lane >> 2) + rp * 8;
                int n = kt * 128 + warp_n * 32 + na * 8 + (lane & 3) * 2;
                float2 v; v.x = acc[na][rp * 2]; v.y = acc[na][rp * 2 + 1];
                *(float2*)(sS + m * 1028 + n) = v;
            }
        if (kt < 7) {
            char* bn = sm + FA_K + ((kt + 1) & 1) * FA_KBUF;
#pragma unroll
            for (int t = 0; t < 8; t++) {
                int idx = tid + t * 256;
                int side = idx >> 10, r = (idx >> 3) & 127, c = idx & 7;
                *(uint4*)(bn + side * FA_KLO + r * LDA64 + c * 16) = kreg[t];
            }
        }
        __syncthreads();
    }

    // -------- phase 2: softmax + mix; write prob to gmem AND p into sS ----
    float l1 = *l1p, l0 = 1.0f - l1;
#pragma unroll
    for (int rr = 0; rr < 4; rr++) {
        int row = wid * 4 + rr;
        const unsigned char* mrow = g_mask + ((size_t)b * Ss + q0 + row) * Ss;
        float v[32];
        float mx = -3e38f;
#pragma unroll
        for (int j = 0; j < 8; j++) {
            int col = lane * 4 + j * 128;
            float4 s4 = *(const float4*)(sS + row * 1028 + col);
            uchar4 mk = *(const uchar4*)(mrow + col);
            v[j * 4 + 0] = mk.x ? -1000000000.0f : s4.x * 0.125f;
            v[j * 4 + 1] = mk.y ? -1000000000.0f : s4.y * 0.125f;
            v[j * 4 + 2] = mk.z ? -1000000000.0f : s4.z * 0.125f;
            v[j * 4 + 3] = mk.w ? -1000000000.0f : s4.w * 0.125f;
#pragma unroll
            for (int u = 0; u < 4; u++) mx = fmaxf(mx, v[j * 4 + u]);
        }
#pragma unroll
        for (int o = 16; o; o >>= 1) mx = fmaxf(mx, __shfl_xor_sync(0xffffffffu, mx, o));
        float sum = 0.0f;
#pragma unroll
        for (int u = 0; u < 32; u++) { v[u] = fexp(v[u] - mx); sum += v[u]; }
#pragma unroll
        for (int o = 16; o; o >>= 1) sum += __shfl_xor_sync(0xffffffffu, sum, o);
        float iv = l0 / sum;
        const float* rrow = g_rel + ((size_t)b * Ss + q0 + row) * Ss;
        float* prow = probp + (bh * Ss + q0 + row) * Ss;
#pragma unroll
        for (int j = 0; j < 8; j++) {
            int col = lane * 4 + j * 128;
            float4 ra4 = *(const float4*)(rrow + col);
            float4 o;
            o.x = fmaf(v[j * 4 + 0], iv, l1 * ra4.x);
            o.y = fmaf(v[j * 4 + 1], iv, l1 * ra4.y);
            o.z = fmaf(v[j * 4 + 2], iv, l1 * ra4.z);
            o.w = fmaf(v[j * 4 + 3], iv, l1 * ra4.w);
            *(float4*)(prow + col) = o;
            *(float4*)(sS + row * 1028 + col) = o;   // keep p for phase 3
        }
    }
    __syncthreads();

    // -------- phase 3: out = P @ V (quarters of K, dbl-buffered V) --------
    const __nv_bfloat16* Vhi = g_Vthi + bh * (size_t)HDd * Ss;
    const __nv_bfloat16* Vlo = g_Vtlo + bh * (size_t)HDd * Ss;
    float oacc[2][4];
#pragma unroll
    for (int nb = 0; nb < 2; nb++)
#pragma unroll
        for (int r = 0; r < 4; r++) oacc[nb][r] = 0.0f;
    // phase3 warp grid: 2m x 4n over out 32x64 (warp tile 16q x 16hd)

    for (int qt = 0; qt < 4; qt++) {
        // convert P quarter 32x256 -> bf16 hi/lo
#pragma unroll
        for (int t = 0; t < 8; t++) {
            int idx = tid + t * 256;
            int r = idx >> 6, c4 = (idx & 63) * 4;
            float4 f = *(const float4*)(sS + r * 1028 + qt * 256 + c4);
            cvt8(sm + FA_P, sm + FA_P + FA_PLO, (unsigned)(r * LDP + c4 * 2), f);
        }
        // V chunk 0 of this quarter
        uint4 vreg[2];
#pragma unroll
        for (int t = 0; t < 2; t++) {
            int idx = tid + t * 256;
            int side = idx >> 8, r = (idx >> 2) & 63, c = idx & 3;
            const __nv_bfloat16* src = (side ? Vlo : Vhi) + (size_t)r * Ss + qt * 256 + c * 8;
            vreg[t] = *(const uint4*)src;
        }
#pragma unroll
        for (int t = 0; t < 2; t++) {
            int idx = tid + t * 256;
            int side = idx >> 8, r = (idx >> 2) & 63, c = idx & 3;
            *(uint4*)(sm + FA_V + side * FA_VLO + r * LDA + c * 16) = vreg[t];
        }
        __syncthreads();

        for (int sub = 0; sub < 8; sub++) {
            if (sub < 7) {
#pragma unroll
                for (int t = 0; t < 2; t++) {
                    int idx = tid + t * 256;
                    int side = idx >> 8, r = (idx >> 2) & 63, c = idx & 3;
                    const __nv_bfloat16* src = (side ? Vlo : Vhi) + (size_t)r * Ss + qt * 256 + (sub + 1) * 32 + c * 8;
                    vreg[t] = *(const uint4*)src;
                }
            }
            unsigned aOff = smb + FA_P + (unsigned)(warp_m * 16 + (lane & 15)) * LDP
                          + ((lane >> 4) & 1) * 16 + sub * 64;
            unsigned bOff = smb + FA_V + (unsigned)(sub & 1) * FA_VBUF
                          + (unsigned)(warp_n * 16 + (lane & 7)) * LDA + ((lane >> 3) & 1) * 16;
#pragma unroll
            for (int ks = 0; ks < 2; ks++) {
                unsigned ah[4], al[4];
                ldmA(ah, aOff + ks * 32);
                ldmA(al, aOff + FA_PLO + ks * 32);
#pragma unroll
                for (int nb = 0; nb < 2; nb++) {
                    unsigned bhF[2], blF[2];
                    ldmB(bhF, bOff + nb * 8 * LDA + ks * 32);
                    ldmB(blF, bOff + FA_VLO + nb * 8 * LDA + ks * 32);
                    mma16816(oacc[nb], ah, bhF);
                    mma16816(oacc[nb], ah, blF);
                    mma16816(oacc[nb], al, bhF);
                }
            }
            if (sub < 7) {
                char* vb = sm + FA_V + ((sub + 1) & 1) * FA_VBUF;
#pragma unroll
                for (int t = 0; t < 2; t++) {
                    int idx = tid + t * 256;
                    int side = idx >> 8, r = (idx >> 2) & 63, c = idx & 3;
                    *(uint4*)(vb + side * FA_VLO + r * LDA + c * 16) = vreg[t];
                }
            }
            __syncthreads();
        }
    }

    // epilogue: out 32x64
#pragma unroll
    for (int nb = 0; nb < 2; nb++)
#pragma unroll
        for (int rp = 0; rp < 2; rp++) {
            int m = warp_m * 16 + (lane >> 2) + rp * 8;
            int n = warp_n * 16 + nb * 8 + (lane & 3) * 2;
            float2 v;
            v.x = oacc[nb][rp * 2];
            v.y = oacc[nb][rp * 2 + 1];
            *(float2*)(outp + ((size_t)b * Ss + q0 + m) * Dd + h * HDd + n) = v;
        }
}

// ---------------- launcher ----------------------------------------------
extern "C" void kernel_launch(void* const* d_in, const int* in_sizes, int n_in,
                              void* d_out, int out_size) {
    const float* q   = (const float*)d_in[0];
    const float* k   = (const float*)d_in[1];
    const float* v   = (const float*)d_in[2];
    const float* rel = (const float*)d_in[3];
    const void*  msk = d_in[4];
    const float* l1  = (const float*)d_in[5];
    const float* Wq  = (const float*)d_in[6];
    const float* bq  = (const float*)d_in[7];
    const float* Wk  = (const float*)d_in[8];
    const float* bk  = (const float*)d_in[9];
    const float* Wv  = (const float*)d_in[10];
    const float* bv  = (const float*)d_in[11];

    float* outp = (float*)d_out;
    float* probp = outp + (size_t)Bb * Ss * Dd;

    cudaFuncSetAttribute(proj_mma,   cudaFuncAttributeMaxDynamicSharedMemorySize, PROJ_SMEM);
    cudaFuncSetAttribute(fused_attn, cudaFuncAttributeMaxDynamicSharedMemorySize, FA_SMEM);

    mask_detect_kernel<<<1, 256>>>(msk);
    mask_convert_kernel<<<(Bb * Ss * Ss) / 256, 256>>>(msk);

    rel_softmax_kernel<<<Bb * Ss, 256>>>(rel);

    dim3 gp(Dd / 128, (Bb * Ss) / 128, 3);
    proj_mma<<<gp, 256, PROJ_SMEM>>>(q, k, v, Wq, Wk, Wv, bq, bk, bv);

    dim3 gf(Ss / 32, Hh, Bb);
    fused_attn<<<gf, 256, FA_SMEM>>>(l1, probp, outp);
}

// round 13
// speedup vs baseline: 1.1420x; 1.1420x over previous
#include <cuda_runtime.h>
#include <cuda_bf16.h>
#include <cstdint>

#define Bb 8
#define Ss 1024
#define Dd 768
#define Hh 12
#define HDd 64
#define BH (Bb*Hh)
#define LDA 80    // 32 bf16 + 8B pad
#define LDA64 144 // 64 bf16 + 16B pad

// ---------------- device scratch (statics; no runtime allocs) ------------
__device__ __nv_bfloat16 g_Qhi[(size_t)BH * Ss * HDd];
__device__ __nv_bfloat16 g_Qlo[(size_t)BH * Ss * HDd];
__device__ __nv_bfloat16 g_Khi[(size_t)BH * Ss * HDd];
__device__ __nv_bfloat16 g_Klo[(size_t)BH * Ss * HDd];
__device__ __nv_bfloat16 g_Vthi[(size_t)BH * HDd * Ss];   // [B,H,HD,S]
__device__ __nv_bfloat16 g_Vtlo[(size_t)BH * HDd * Ss];
__device__ float g_rel[(size_t)Bb * Ss * Ss];             // rel_attn (head-indep)
__device__ unsigned char g_mask[(size_t)Bb * Ss * Ss];
__device__ int g_mmode;

// ======================= MMA primitives (plain sm_80+ PTX) ===============
__device__ __forceinline__ unsigned smem_u32(const void* p) {
    unsigned a;
    asm("{ .reg .u64 t; cvta.to.shared.u64 t, %1; cvt.u32.u64 %0, t; }" : "=r"(a) : "l"(p));
    return a;
}
__device__ __forceinline__ void ldmA(unsigned* a, unsigned addr) {
    asm volatile("ldmatrix.sync.aligned.m8n8.x4.shared.b16 {%0,%1,%2,%3}, [%4];"
        : "=r"(a[0]), "=r"(a[1]), "=r"(a[2]), "=r"(a[3]) : "r"(addr));
}
__device__ __forceinline__ void ldmB(unsigned* b, unsigned addr) {
    asm volatile("ldmatrix.sync.aligned.m8n8.x2.shared.b16 {%0,%1}, [%2];"
        : "=r"(b[0]), "=r"(b[1]) : "r"(addr));
}
__device__ __forceinline__ void mma16816(float* d, const unsigned* a, const unsigned* b) {
    asm volatile("mma.sync.aligned.m16n8k16.row.col.f32.bf16.bf16.f32 "
        "{%0,%1,%2,%3}, {%4,%5,%6,%7}, {%8,%9}, {%0,%1,%2,%3};"
        : "+f"(d[0]), "+f"(d[1]), "+f"(d[2]), "+f"(d[3])
        : "r"(a[0]), "r"(a[1]), "r"(a[2]), "r"(a[3]), "r"(b[0]), "r"(b[1]));
}

// fp32 -> bf16 hi/lo split; store 4 elems (8B) per side at byte offset 'off'
__device__ __forceinline__ void cvt8(char* hi, char* lo, unsigned off, float4 f) {
    __nv_bfloat162 h0 = __float22bfloat162_rn(make_float2(f.x, f.y));
    __nv_bfloat162 h1 = __float22bfloat162_rn(make_float2(f.z, f.w));
    float2 g0 = __bfloat1622float2(h0);
    float2 g1 = __bfloat1622float2(h1);
    __nv_bfloat162 m0 = __float22bfloat162_rn(make_float2(f.x - g0.x, f.y - g0.y));
    __nv_bfloat162 m1 = __float22bfloat162_rn(make_float2(f.z - g1.x, f.w - g1.y));
    uint2 uh; uh.x = *(unsigned*)&h0; uh.y = *(unsigned*)&h1;
    uint2 ul; ul.x = *(unsigned*)&m0; ul.y = *(unsigned*)&m1;
    *(uint2*)(hi + off) = uh;
    *(uint2*)(lo + off) = ul;
}

template<int NF4> struct R4 { float4 v[NF4]; };
template<int NF4>
__device__ __forceinline__ void gload(const float* __restrict__ src, int stride, R4<NF4>& rg, int tid) {
#pragma unroll
    for (int t = 0; t < NF4; t++) {
        int i = tid + t * 256;
        rg.v[t] = *(const float4*)(src + (long)(i >> 3) * stride + (i & 7) * 4);
    }
}
template<int NF4>
__device__ __forceinline__ void cstore(char* hi, char* lo, const R4<NF4>& rg, int tid) {
#pragma unroll
    for (int t = 0; t < NF4; t++) {
        int i = tid + t * 256;
        cvt8(hi, lo, (unsigned)((i >> 3) * LDA + (i & 7) * 8), rg.v[t]);
    }
}

// one K=32 chunk of 3-pass split MMA; A 128 rows, B NBROWS rows (LDA=80)
template<int NAT, int NBROWS>
__device__ __forceinline__ void mma_chunk(float (&c)[4][NAT][4], unsigned sb,
                                          int lane, int warp_m, int warp_n) {
    unsigned aOff = sb + (unsigned)(warp_m * 64 + (lane & 15)) * LDA + ((lane >> 4) & 1) * 16;
    unsigned bOff = sb + 20480u + (unsigned)(warp_n * (NAT * 8) + (lane & 7)) * LDA + ((lane >> 3) & 1) * 16;
#pragma unroll
    for (int ks = 0; ks < 2; ks++) {
        unsigned ah[4][4], al[4][4];
#pragma unroll
        for (int ma = 0; ma < 4; ma++) {
            ldmA(ah[ma], aOff + ma * 16 * LDA + ks * 32);
            ldmA(al[ma], aOff + 10240u + ma * 16 * LDA + ks * 32);
        }
#pragma unroll
        for (int na = 0; na < NAT; na++) {
            unsigned bh[2], bl[2];
            ldmB(bh, bOff + na * 8 * LDA + ks * 32);
            ldmB(bl, bOff + (unsigned)NBROWS * LDA + na * 8 * LDA + ks * 32);
#pragma unroll
            for (int ma = 0; ma < 4; ma++) {
                mma16816(c[ma][na], ah[ma], bh);
                mma16816(c[ma][na], ah[ma], bl);
                mma16816(c[ma][na], al[ma], bh);
            }
        }
    }
}

// fast exp on the FFMA pipe (~1.3e-5 rel err)
__device__ __forceinline__ float fexp(float x) {
    float t = fmaxf(x * 1.4426950408889634f, -126.0f);
    float fi = floorf(t);
    float f = t - fi;
    float p = 1.5403530394e-4f;
    p = fmaf(p, f, 1.3333558146e-3f);
    p = fmaf(p, f, 9.6181291076e-3f);
    p = fmaf(p, f, 5.5504108664e-2f);
    p = fmaf(p, f, 2.4022650696e-1f);
    p = fmaf(p, f, 6.9314718056e-1f);
    p = fmaf(p, f, 1.0f);
    return p * __int_as_float(((int)fi + 127) << 23);
}

__device__ __forceinline__ void split1(float v, __nv_bfloat16& h, __nv_bfloat16& l) {
    h = __float2bfloat16(v);
    l = __float2bfloat16(v - __bfloat162float(h));
}

// ---------------- mask detect + convert ----------------------------------
__global__ void mask_detect_kernel(const void* mp) {
    __shared__ int allf, alli;
    if (threadIdx.x == 0) { allf = 1; alli = 1; }
    __syncthreads();
    float v = ((const float*)mp)[threadIdx.x];
    int iv = ((const int*)mp)[threadIdx.x];
    if (!(v == 0.0f || v == 1.0f)) allf = 0;
    if (!(iv == 0 || iv == 1)) alli = 0;
    __syncthreads();
    if (threadIdx.x == 0) g_mmode = allf ? 0 : (alli ? 1 : 2);
}
__global__ void mask_convert_kernel(const void* mp) {
    size_t i = (size_t)blockIdx.x * blockDim.x + threadIdx.x;
    int mode = g_mmode;
    unsigned char m;
    if (mode == 0)      m = (((const float*)mp)[i] != 0.0f);
    else if (mode == 1) m = (((const int*)mp)[i] != 0);
    else                m = (((const unsigned char*)mp)[i] != 0);
    g_mask[i] = m;
}

// ---------------- rel_attn softmax (head-independent) --------------------
__global__ void __launch_bounds__(256)
rel_softmax_kernel(const float* __restrict__ rel) {
    __shared__ float red[8];
    int row = blockIdx.x;
    const float* r = rel + (size_t)row * Ss;
    const unsigned char* m = g_mask + (size_t)row * Ss;
    int tid = threadIdx.x, w = tid >> 5, l = tid & 31;

    float4 rf = *(const float4*)(r + tid * 4);
    uchar4 mk = *(const uchar4*)(m + tid * 4);
    float v[4];
    v[0] = mk.x ? rf.x : 0.0f; v[1] = mk.y ? rf.y : 0.0f;
    v[2] = mk.z ? rf.z : 0.0f; v[3] = mk.w ? rf.w : 0.0f;
    float mx = -3e38f;
#pragma unroll
    for (int j = 0; j < 4; j++) {
        v[j] = (v[j] == 0.0f) ? -10000.0f : v[j];
        mx = fmaxf(mx, v[j]);
    }
#pragma unroll
    for (int o = 16; o; o >>= 1) mx = fmaxf(mx, __shfl_xor_sync(0xffffffffu, mx, o));
    if (l == 0) red[w] = mx;
    __syncthreads();
    if (w == 0) {
        float t = (l < 8) ? red[l] : -3e38f;
#pragma unroll
        for (int o = 4; o; o >>= 1) t = fmaxf(t, __shfl_xor_sync(0xffffffffu, t, o));
        if (l == 0) red[0] = t;
    }
    __syncthreads();
    mx = red[0];
    __syncthreads();
    float e[4], sum = 0.0f;
#pragma unroll
    for (int j = 0; j < 4; j++) { e[j] = fexp(v[j] - mx); sum += e[j]; }
#pragma unroll
    for (int o = 16; o; o >>= 1) sum += __shfl_xor_sync(0xffffffffu, sum, o);
    if (l == 0) red[w] = sum;
    __syncthreads();
    if (w == 0) {
        float t = (l < 8) ? red[l] : 0.0f;
#pragma unroll
        for (int o = 4; o; o >>= 1) t += __shfl_xor_sync(0xffffffffu, t, o);
        if (l == 0) red[0] = t;
    }
    __syncthreads();
    float inv = 1.0f / red[0];
    float4 o;
    o.x = e[0] * inv; o.y = e[1] * inv; o.z = e[2] * inv; o.w = e[3] * inv;
    *(float4*)(g_rel + (size_t)row * Ss + tid * 4) = o;
}

// ================= projection GEMM (bf16x3 mma.sync) =====================
// Writes pre-split bf16 hi/lo: Q,K -> [B,H,S,HD]; V -> transposed [B,H,HD,S]
#define PROJ_SMEM (2 * 40960)
__global__ void __launch_bounds__(256, 1)
proj_mma(const float* __restrict__ Xq, const float* __restrict__ Xk, const float* __restrict__ Xv,
         const float* __restrict__ Wq, const float* __restrict__ Wk, const float* __restrict__ Wv,
         const float* __restrict__ bqp, const float* __restrict__ bkp, const float* __restrict__ bvp) {
    extern __shared__ char sm[];
    unsigned smb = smem_u32(sm);
    int tid = threadIdx.x, lane = tid & 31, wid = tid >> 5;
    int warp_m = wid >> 2, warp_n = wid & 3;
    int z = blockIdx.z;
    const float* X = (z == 0) ? Xq : (z == 1) ? Xk : Xv;
    const float* W = (z == 0) ? Wq : (z == 1) ? Wk : Wv;
    const float* bias = (z == 0) ? bqp : (z == 1) ? bkp : bvp;
    int j0 = blockIdx.x * 128, i0 = blockIdx.y * 128;

    float acc[4][4][4];
#pragma unroll
    for (int a = 0; a < 4; a++)
#pragma unroll
        for (int b = 0; b < 4; b++)
#pragma unroll
            for (int r = 0; r < 4; r++) acc[a][b][r] = 0.0f;

    const float* A0 = X + (size_t)i0 * Dd;
    const float* B0 = W + (size_t)j0 * Dd;
    R4<4> ra, rb;
    gload<4>(A0, Dd, ra, tid);
    gload<4>(B0, Dd, rb, tid);
    cstore<4>(sm, sm + 10240, ra, tid);
    cstore<4>(sm + 20480, sm + 30720, rb, tid);
    __syncthreads();

    const int NC = Dd / 32;
    for (int cc = 0; cc < NC; cc++) {
        if (cc + 1 < NC) {
            gload<4>(A0 + (cc + 1) * 32, Dd, ra, tid);
            gload<4>(B0 + (cc + 1) * 32, Dd, rb, tid);
        }
        mma_chunk<4, 128>(acc, smb + (unsigned)(cc & 1) * 40960u, lane, warp_m, warp_n);
        if (cc + 1 < NC) {
            char* bn = sm + ((cc + 1) & 1) * 40960;
            cstore<4>(bn, bn + 10240, ra, tid);
            cstore<4>(bn + 20480, bn + 30720, rb, tid);
        }
        __syncthreads();
    }

    int bI = i0 >> 10, sbase = i0 & 1023;
    float bias2[4][2];
#pragma unroll
    for (int na = 0; na < 4; na++) {
        int n0 = warp_n * 32 + na * 8 + (lane & 3) * 2;
        bias2[na][0] = bias[j0 + n0];
        bias2[na][1] = bias[j0 + n0 + 1];
    }
    if (z == 2) {
#pragma unroll
        for (int ma = 0; ma < 4; ma++)
#pragma unroll
            for (int na = 0; na < 4; na++)
#pragma unroll
                for (int rp = 0; rp < 2; rp++) {
                    int m = warp_m * 64 + ma * 16 + (lane >> 2) + rp * 8;
                    int n0 = warp_n * 32 + na * 8 + (lane & 3) * 2;
                    int j = j0 + n0, h = j >> 6, hd = j & 63;
                    int s = sbase + m;
                    float v0 = acc[ma][na][rp * 2]     + bias2[na][0];
                    float v1 = acc[ma][na][rp * 2 + 1] + bias2[na][1];
                    __nv_bfloat16 h0, l0, h1, l1;
                    split1(v0, h0, l0); split1(v1, h1, l1);
                    size_t base = ((size_t)bI * Hh + h) * HDd;
                    g_Vthi[(base + hd)     * Ss + s] = h0;
                    g_Vtlo[(base + hd)     * Ss + s] = l0;
                    g_Vthi[(base + hd + 1) * Ss + s] = h1;
                    g_Vtlo[(base + hd + 1) * Ss + s] = l1;
                }
    } else {
        __nv_bfloat16* Ohi = (z == 0) ? g_Qhi : g_Khi;
        __nv_bfloat16* Olo = (z == 0) ? g_Qlo : g_Klo;
#pragma unroll
        for (int ma = 0; ma < 4; ma++)
#pragma unroll
            for (int na = 0; na < 4; na++)
#pragma unroll
                for (int rp = 0; rp < 2; rp++) {
                    int m = warp_m * 64 + ma * 16 + (lane >> 2) + rp * 8;
                    int n0 = warp_n * 32 + na * 8 + (lane & 3) * 2;
                    int j = j0 + n0, h = j >> 6, hd = j & 63;
                    float v0 = acc[ma][na][rp * 2]     + bias2[na][0];
                    float v1 = acc[ma][na][rp * 2 + 1] + bias2[na][1];
                    __nv_bfloat16 h0, l0, h1, l1;
                    split1(v0, h0, l0); split1(v1, h1, l1);
                    size_t idx = (((size_t)bI * Hh + h) * Ss + sbase + m) * HDd + hd;
                    __nv_bfloat162 ph; ph.x = h0; ph.y = h1;
                    __nv_bfloat162 pl; pl.x = l0; pl.y = l1;
                    *(__nv_bfloat162*)(Ohi + idx) = ph;
                    *(__nv_bfloat162*)(Olo + idx) = pl;
                }
    }
}

// ====== fused attention: QK^T -> mask/scale -> softmax -> mix -> prob =====
// block = (qtile 32, h, b); 256 threads; scores 32x1028 fp32 in SMEM.
// SMEM: [scores 131584][Q hi/lo 9216][K dbl-buf 2x36864] = 214528
#define FA_Q     131584
#define FA_K     140800
#define FA_KLO   18432
#define FA_KBUF  36864
#define FA_SMEM  214528
__global__ void __launch_bounds__(256, 1)
fused_attn(const float* __restrict__ l1p, float* __restrict__ probp) {
    extern __shared__ char sm[];
    unsigned smb = smem_u32(sm);
    float* sS = (float*)sm;
    int tid = threadIdx.x, lane = tid & 31, wid = tid >> 5;
    int warp_m = wid >> 2, warp_n = wid & 3;   // 2x4 (16q x 32k)
    int q0 = blockIdx.x * 32, h = blockIdx.y, b = blockIdx.z;
    size_t bh = (size_t)b * Hh + h;

    // ---- load Q tile (pre-split): 512 uint4 copies ----
    {
        const __nv_bfloat16* qs[2] = { g_Qhi + (bh * Ss + q0) * HDd, g_Qlo + (bh * Ss + q0) * HDd };
#pragma unroll
        for (int t = 0; t < 2; t++) {
            int idx = tid + t * 256;
            int side = idx >> 8, r = (idx >> 3) & 31, c = idx & 7;
            uint4 u = *(const uint4*)(qs[side] + (size_t)r * HDd + c * 8);
            *(uint4*)(sm + FA_Q + side * 4608 + r * LDA64 + c * 16) = u;
        }
    }
    // ---- K tile 0 ----
    const __nv_bfloat16* Khi = g_Khi + bh * Ss * HDd;
    const __nv_bfloat16* Klo = g_Klo + bh * Ss * HDd;
    uint4 kreg[8];
#pragma unroll
    for (int t = 0; t < 8; t++) {
        int idx = tid + t * 256;
        int side = idx >> 10, r = (idx >> 3) & 127, c = idx & 7;
        kreg[t] = *(const uint4*)((side ? Klo : Khi) + (size_t)r * HDd + c * 8);
    }
#pragma unroll
    for (int t = 0; t < 8; t++) {
        int idx = tid + t * 256;
        int side = idx >> 10, r = (idx >> 3) & 127, c = idx & 7;
        *(uint4*)(sm + FA_K + side * FA_KLO + r * LDA64 + c * 16) = kreg[t];
    }
    __syncthreads();

    unsigned aBase = smb + FA_Q + (unsigned)(warp_m * 16 + (lane & 15)) * LDA64 + ((lane >> 4) & 1) * 16;
    // ---------------- phase 1: raw scores into SMEM ----------------
    for (int kt = 0; kt < 8; kt++) {
        if (kt < 7) {
#pragma unroll
            for (int t = 0; t < 8; t++) {
                int idx = tid + t * 256;
                int side = idx >> 10, r = (idx >> 3) & 127, c = idx & 7;
                kreg[t] = *(const uint4*)((side ? Klo : Khi) + ((size_t)(kt + 1) * 128 + r) * HDd + c * 8);
            }
        }
        unsigned bBase = smb + FA_K + (unsigned)(kt & 1) * FA_KBUF
                       + (unsigned)(warp_n * 32 + (lane & 7)) * LDA64 + ((lane >> 3) & 1) * 16;
        float acc[4][4];
#pragma unroll
        for (int na = 0; na < 4; na++)
#pragma unroll
            for (int r = 0; r < 4; r++) acc[na][r] = 0.0f;
#pragma unroll
        for (int ks = 0; ks < 4; ks++) {
            unsigned ah[4], al[4];
            ldmA(ah, aBase + ks * 32);
            ldmA(al, aBase + 4608 + ks * 32);
#pragma unroll
            for (int na = 0; na < 4; na++) {
                unsigned bhF[2], blF[2];
                ldmB(bhF, bBase + na * 8 * LDA64 + ks * 32);
                ldmB(blF, bBase + FA_KLO + na * 8 * LDA64 + ks * 32);
                mma16816(acc[na], ah, bhF);
                mma16816(acc[na], ah, blF);
                mma16816(acc[na], al, bhF);
            }
        }
#pragma unroll
        for (int na = 0; na < 4; na++)
#pragma unroll
            for (int rp = 0; rp < 2; rp++) {
                int m = warp_m * 16 + (lane >> 2) + rp * 8;
                int n = kt * 128 + warp_n * 32 + na * 8 + (lane & 3) * 2;
                float2 v; v.x = acc[na][rp * 2]; v.y = acc[na][rp * 2 + 1];
                *(float2*)(sS + m * 1028 + n) = v;
            }
        if (kt < 7) {
            char* bn = sm + FA_K + ((kt + 1) & 1) * FA_KBUF;
#pragma unroll
            for (int t = 0; t < 8; t++) {
                int idx = tid + t * 256;
                int side = idx >> 10, r = (idx >> 3) & 127, c = idx & 7;
                *(uint4*)(bn + side * FA_KLO + r * LDA64 + c * 16) = kreg[t];
            }
        }
        __syncthreads();
    }

    // -------- phase 2: softmax + mix + prob write --------
    float l1 = *l1p, l0 = 1.0f - l1;
#pragma unroll
    for (int rr = 0; rr < 4; rr++) {
        int row = wid * 4 + rr;
        const unsigned char* mrow = g_mask + ((size_t)b * Ss + q0 + row) * Ss;
        float v[32];
        float mx = -3e38f;
#pragma unroll
        for (int j = 0; j < 8; j++) {
            int col = lane * 4 + j * 128;
            float4 s4 = *(const float4*)(sS + row * 1028 + col);
            uchar4 mk = *(const uchar4*)(mrow + col);
            v[j * 4 + 0] = mk.x ? -1000000000.0f : s4.x * 0.125f;
            v[j * 4 + 1] = mk.y ? -1000000000.0f : s4.y * 0.125f;
            v[j * 4 + 2] = mk.z ? -1000000000.0f : s4.z * 0.125f;
            v[j * 4 + 3] = mk.w ? -1000000000.0f : s4.w * 0.125f;
#pragma unroll
            for (int u = 0; u < 4; u++) mx = fmaxf(mx, v[j * 4 + u]);
        }
#pragma unroll
        for (int o = 16; o; o >>= 1) mx = fmaxf(mx, __shfl_xor_sync(0xffffffffu, mx, o));
        float sum = 0.0f;
#pragma unroll
        for (int u = 0; u < 32; u++) { v[u] = fexp(v[u] - mx); sum += v[u]; }
#pragma unroll
        for (int o = 16; o; o >>= 1) sum += __shfl_xor_sync(0xffffffffu, sum, o);
        float iv = l0 / sum;
        const float* rrow = g_rel + ((size_t)b * Ss + q0 + row) * Ss;
        float* prow = probp + (bh * Ss + q0 + row) * Ss;
#pragma unroll
        for (int j = 0; j < 8; j++) {
            int col = lane * 4 + j * 128;
            float4 ra4 = *(const float4*)(rrow + col);
            float4 o;
            o.x = fmaf(v[j * 4 + 0], iv, l1 * ra4.x);
            o.y = fmaf(v[j * 4 + 1], iv, l1 * ra4.y);
            o.z = fmaf(v[j * 4 + 2], iv, l1 * ra4.z);
            o.w = fmaf(v[j * 4 + 3], iv, l1 * ra4.w);
            *(float4*)(prow + col) = o;
        }
    }
}

// ================= PV GEMM: out = P @ V ==================================
// tile 128(q) x 64(hd); A = prob fp32 (split on load), B = pre-split g_Vt
#define PV_SMEM (2 * 30720)
__global__ void __launch_bounds__(256, 1)
pv_mma(const float* __restrict__ probp, float* __restrict__ outp) {
    extern __shared__ char sm[];
    unsigned smb = smem_u32(sm);
    int tid = threadIdx.x, lane = tid & 31, wid = tid >> 5;
    int warp_m = wid >> 2, warp_n = wid & 3;
    int q0 = blockIdx.x * 128, bh = blockIdx.y;
    int b_ = bh / Hh, h_ = bh % Hh;

    float acc[4][2][4];
#pragma unroll
    for (int a = 0; a < 4; a++)
#pragma unroll
        for (int b = 0; b < 2; b++)
#pragma unroll
            for (int r = 0; r < 4; r++) acc[a][b][r] = 0.0f;

    const float* A0 = probp + ((size_t)bh * Ss + q0) * Ss;
    const __nv_bfloat16* Vhi = g_Vthi + (size_t)bh * HDd * Ss;
    const __nv_bfloat16* Vlo = g_Vtlo + (size_t)bh * HDd * Ss;

    R4<4> ra;
    uint4 vreg[2];
    gload<4>(A0, Ss, ra, tid);
#pragma unroll
    for (int t = 0; t < 2; t++) {
        int idx = tid + t * 256;
        int side = idx >> 8, r = (idx >> 2) & 63, c = idx & 3;
        vreg[t] = *(const uint4*)((side ? Vlo : Vhi) + (size_t)r * Ss + c * 8);
    }
    cstore<4>(sm, sm + 10240, ra, tid);
#pragma unroll
    for (int t = 0; t < 2; t++) {
        int idx = tid + t * 256;
        int side = idx >> 8, r = (idx >> 2) & 63, c = idx & 3;
        *(uint4*)(sm + 20480 + side * 5120 + r * LDA + c * 16) = vreg[t];
    }
    __syncthreads();

    const int NC = Ss / 32;
    for (int cc = 0; cc < NC; cc++) {
        if (cc + 1 < NC) {
            gload<4>(A0 + (cc + 1) * 32, Ss, ra, tid);
#pragma unroll
            for (int t = 0; t < 2; t++) {
                int idx = tid + t * 256;
                int side = idx >> 8, r = (idx >> 2) & 63, c = idx & 3;
                vreg[t] = *(const uint4*)((side ? Vlo : Vhi) + (size_t)r * Ss + (cc + 1) * 32 + c * 8);
            }
        }
        mma_chunk<2, 64>(acc, smb + (unsigned)(cc & 1) * 30720u, lane, warp_m, warp_n);
        if (cc + 1 < NC) {
            char* bn = sm + ((cc + 1) & 1) * 30720;
            cstore<4>(bn, bn + 10240, ra, tid);
#pragma unroll
            for (int t = 0; t < 2; t++) {
                int idx = tid + t * 256;
                int side = idx >> 8, r = (idx >> 2) & 63, c = idx & 3;
                *(uint4*)(bn + 20480 + side * 5120 + r * LDA + c * 16) = vreg[t];
            }
        }
        __syncthreads();
    }

#pragma unroll
    for (int ma = 0; ma < 4; ma++)
#pragma unroll
        for (int na = 0; na < 2; na++)
#pragma unroll
            for (int rp = 0; rp < 2; rp++) {
                int m = warp_m * 64 + ma * 16 + (lane >> 2) + rp * 8;
                int n0 = warp_n * 16 + na * 8 + (lane & 3) * 2;
                float2 v;
                v.x = acc[ma][na][rp * 2];
                v.y = acc[ma][na][rp * 2 + 1];
                *(float2*)(outp + ((size_t)b_ * Ss + q0 + m) * Dd + h_ * HDd + n0) = v;
            }
}

// ---------------- launcher ----------------------------------------------
extern "C" void kernel_launch(void* const* d_in, const int* in_sizes, int n_in,
                              void* d_out, int out_size) {
    const float* q   = (const float*)d_in[0];
    const float* k   = (const float*)d_in[1];
    const float* v   = (const float*)d_in[2];
    const float* rel = (const float*)d_in[3];
    const void*  msk = d_in[4];
    const float* l1  = (const float*)d_in[5];
    const float* Wq  = (const float*)d_in[6];
    const float* bq  = (const float*)d_in[7];
    const float* Wk  = (const float*)d_in[8];
    const float* bk  = (const float*)d_in[9];
    const float* Wv  = (const float*)d_in[10];
    const float* bv  = (const float*)d_in[11];

    float* outp = (float*)d_out;
    float* probp = outp + (size_t)Bb * Ss * Dd;

    cudaFuncSetAttribute(proj_mma,   cudaFuncAttributeMaxDynamicSharedMemorySize, PROJ_SMEM);
    cudaFuncSetAttribute(fused_attn, cudaFuncAttributeMaxDynamicSharedMemorySize, FA_SMEM);
    cudaFuncSetAttribute(pv_mma,     cudaFuncAttributeMaxDynamicSharedMemorySize, PV_SMEM);

    mask_detect_kernel<<<1, 256>>>(msk);
    mask_convert_kernel<<<(Bb * Ss * Ss) / 256, 256>>>(msk);

    rel_softmax_kernel<<<Bb * Ss, 256>>>(rel);

    dim3 gp(Dd / 128, (Bb * Ss) / 128, 3);
    proj_mma<<<gp, 256, PROJ_SMEM>>>(q, k, v, Wq, Wk, Wv, bq, bk, bv);

    dim3 gf(Ss / 32, Hh, Bb);
    fused_attn<<<gf, 256, FA_SMEM>>>(l1, probp);

    dim3 gv(Ss / 128, BH);
    pv_mma<<<gv, 256, PV_SMEM>>>(probp, outp);
}